// round 12
// baseline (speedup 1.0000x reference)
#include <cuda_runtime.h>
#include <math.h>
#include <stdint.h>

#define B_SZ 2
#define L 1024
#define D 384
#define PATCH_DIM 4096
#define DEPTH 12
#define DSTATE 16
#define DTRANK 24
#define DBL_N 56
#define NTOK (B_SZ * L)   // 2048
#define NCH 8             // scan chunks
#define CHL (L / NCH)     // 128 steps per chunk
#define SCH 8             // chains per scan block

typedef unsigned long long ull;

// ------------------------- scratch (static device) -------------------------
__device__ float g_tok[NTOK * D];
__device__ float g_h[NTOK * D];
__device__ float g_xz[NTOK * 2 * D];
__device__ float g_xc[NTOK * D];
__device__ float g_dbl[NTOK * DBL_N];
__device__ float g_y[NTOK * D];
__device__ float g_P[B_SZ * D * NCH * DSTATE];
__device__ float g_W[B_SZ * D * NCH * DSTATE];

// ------------------------- cp.async + f32x2 helpers ------------------------
__device__ __forceinline__ void cp_async16(uint32_t dst, const void* src, bool pred) {
    int sz = pred ? 16 : 0;
    asm volatile("cp.async.ca.shared.global [%0], [%1], 16, %2;\n"
                 :: "r"(dst), "l"(src), "r"(sz));
}
__device__ __forceinline__ void cp_commit() {
    asm volatile("cp.async.commit_group;\n");
}
template <int N>
__device__ __forceinline__ void cp_wait() {
    asm volatile("cp.async.wait_group %0;\n" :: "n"(N));
}
__device__ __forceinline__ ull pack2(float x, float y) {
    ull r; asm("mov.b64 %0, {%1, %2};" : "=l"(r) : "f"(x), "f"(y)); return r;
}
__device__ __forceinline__ void unpack2(ull v, float& x, float& y) {
    asm("mov.b64 {%0, %1}, %2;" : "=f"(x), "=f"(y) : "l"(v));
}
__device__ __forceinline__ void ffma2(ull& d, ull a, ull b) {
    asm("fma.rn.f32x2 %0, %1, %2, %0;" : "+l"(d) : "l"(a), "l"(b));
}

// ------------------------- pipelined SGEMM 64x64 (vector LDS + FFMA2) ------
#define BM 64
#define BN 64
#define BK 16
#define ASTRIDE 20

struct SmemGemm {
    __align__(16) float As[2][BM * ASTRIDE];
    __align__(16) float Bs[2][BK * BN];
};

__device__ __forceinline__ void gemm_inner(const float* __restrict__ As,
                                           const float* __restrict__ Bsr,
                                           int m0, int n0, ull acc2[4][2])
{
    #pragma unroll
    for (int k4 = 0; k4 < BK; k4 += 4) {
        float4 a[4];
        #pragma unroll
        for (int i = 0; i < 4; i++)
            a[i] = *reinterpret_cast<const float4*>(&As[(m0 + i) * ASTRIDE + k4]);
        #pragma unroll
        for (int q = 0; q < 4; q++) {
            float4 bq = *reinterpret_cast<const float4*>(&Bsr[(k4 + q) * BN + n0]);
            ull b01 = pack2(bq.x, bq.y);
            ull b23 = pack2(bq.z, bq.w);
            #pragma unroll
            for (int i = 0; i < 4; i++) {
                const float* af = &a[i].x;
                ull ap = pack2(af[q], af[q]);
                ffma2(acc2[i][0], ap, b01);
                ffma2(acc2[i][1], ap, b23);
            }
        }
    }
}

// epi: 0 none, 1 +bias, 3 C += result.
// gridDim.z>1 -> split-K, partials accumulated via atomicAdd (bias ignored).
__global__ void sgemm_k(const float* __restrict__ A, int lda,
                        const float* __restrict__ Bm,
                        float* __restrict__ C,
                        const float* __restrict__ bias,
                        int M, int N, int K, int epi)
{
    __shared__ SmemGemm sm;
    const int bm = blockIdx.y * BM, bn = blockIdx.x * BN;
    const int tid = threadIdx.x;

    const int ksplit = gridDim.z;
    const int kc = K / ksplit;
    const int kstart = blockIdx.z * kc;
    const int kend = kstart + kc;
    const int niters = (kc + BK - 1) / BK;

    const int am  = tid >> 2;
    const int akq = (tid & 3) << 2;
    const int bkb = tid >> 4;
    const int bn4 = (tid & 15) << 2;
    const bool bn_ok = (bn + bn4) < N;

    const float* Arow = A + (size_t)(bm + am) * lda;

    uint32_t sAs = (uint32_t)__cvta_generic_to_shared(&sm.As[0][0]);
    uint32_t sBs = (uint32_t)__cvta_generic_to_shared(&sm.Bs[0][0]);

    auto load_stage = [&](int it, int buf) {
        int k0 = kstart + it * BK;
        {
            int k = k0 + akq;
            bool p = k < kend;
            const float* src = p ? (Arow + k) : A;
            cp_async16(sAs + (buf * BM * ASTRIDE + am * ASTRIDE + akq) * 4, src, p);
        }
        {
            int k = k0 + bkb;
            bool p = (k < kend) && bn_ok;
            const float* src = p ? (Bm + (size_t)k * N + bn + bn4) : Bm;
            cp_async16(sBs + (buf * BK * BN + bkb * BN + bn4) * 4, src, p);
        }
    };

    const int ty = tid >> 4, tx = tid & 15;
    const int m0 = ty * 4, n0 = tx * 4;

    ull acc2[4][2];
    #pragma unroll
    for (int i = 0; i < 4; i++) { acc2[i][0] = 0ull; acc2[i][1] = 0ull; }

    load_stage(0, 0); cp_commit();
    if (niters > 1) load_stage(1, 1);
    cp_commit();

    for (int it = 0; it < niters; it++) {
        cp_wait<1>();
        __syncthreads();
        const int buf = it & 1;
        gemm_inner(&sm.As[buf][0], &sm.Bs[buf][0], m0, n0, acc2);
        __syncthreads();
        if (it + 2 < niters) load_stage(it + 2, buf);
        cp_commit();
    }

    #pragma unroll
    for (int i = 0; i < 4; i++) {
        int row = bm + m0 + i;
        float v[4];
        unpack2(acc2[i][0], v[0], v[1]);
        unpack2(acc2[i][1], v[2], v[3]);
        #pragma unroll
        for (int j = 0; j < 4; j++) {
            int col = bn + n0 + j;
            if (col < N) {
                size_t off = (size_t)row * N + col;
                float vv = v[j];
                if (ksplit > 1) {
                    atomicAdd(&C[off], vv);
                } else {
                    if (epi == 1) vv += bias[col];
                    if (epi == 3) vv += C[off];
                    C[off] = vv;
                }
            }
        }
    }
}

// ------------------------- patchify GEMM (im2col fused, split-K) -----------
__global__ void sgemm_patch_k(const float* __restrict__ X,
                              const float* __restrict__ Bm,
                              float* __restrict__ C)
{
    __shared__ SmemGemm sm;
    const int bm = blockIdx.y * BM, bn = blockIdx.x * BN;
    const int tid = threadIdx.x;
    const int N = D;

    const int kc = PATCH_DIM / gridDim.z;
    const int kstart = blockIdx.z * kc;
    const int niters = kc / BK;

    const int am  = tid >> 2;
    const int akq = (tid & 3) << 2;
    const int bkb = tid >> 4;
    const int bn4 = (tid & 15) << 2;

    const int m = bm + am;
    const int b = m >> 10, l = m & 1023;
    const int gh = l >> 6, gw = (l >> 3) & 7, gd = l & 7;
    const size_t xbase = ((size_t)(b * 256 + gh * 16) * 256 + gw * 32) * 64 + gd * 8;

    uint32_t sAs = (uint32_t)__cvta_generic_to_shared(&sm.As[0][0]);
    uint32_t sBs = (uint32_t)__cvta_generic_to_shared(&sm.Bs[0][0]);

    auto load_stage = [&](int it, int buf) {
        int k0 = kstart + it * BK;
        {
            int k = k0 + akq;
            int ph = k >> 8, pw = (k >> 3) & 31, pd = k & 7;
            const float* src = X + xbase + (size_t)ph * 16384 + pw * 64 + pd;
            cp_async16(sAs + (buf * BM * ASTRIDE + am * ASTRIDE + akq) * 4, src, true);
        }
        {
            int k = k0 + bkb;
            const float* src = Bm + (size_t)k * N + bn + bn4;
            cp_async16(sBs + (buf * BK * BN + bkb * BN + bn4) * 4, src, true);
        }
    };

    const int ty = tid >> 4, tx = tid & 15;
    const int m0 = ty * 4, n0 = tx * 4;

    ull acc2[4][2];
    #pragma unroll
    for (int i = 0; i < 4; i++) { acc2[i][0] = 0ull; acc2[i][1] = 0ull; }

    load_stage(0, 0); cp_commit();
    load_stage(1, 1); cp_commit();

    for (int it = 0; it < niters; it++) {
        cp_wait<1>();
        __syncthreads();
        const int buf = it & 1;
        gemm_inner(&sm.As[buf][0], &sm.Bs[buf][0], m0, n0, acc2);
        __syncthreads();
        if (it + 2 < niters) load_stage(it + 2, buf);
        cp_commit();
    }

    #pragma unroll
    for (int i = 0; i < 4; i++) {
        int row = bm + m0 + i;
        float v[4];
        unpack2(acc2[i][0], v[0], v[1]);
        unpack2(acc2[i][1], v[2], v[3]);
        #pragma unroll
        for (int j = 0; j < 4; j++)
            atomicAdd(&C[(size_t)row * N + bn + n0 + j], v[j]);
    }
}

// ------------------------- zero buffer --------------------------------------
__global__ void zero_k(float* __restrict__ p, int n) {
    int i = blockIdx.x * blockDim.x + threadIdx.x;
    if (i < n) p[i] = 0.f;
}

// ------------------------- LayerNorm + xz/dbl zeroing ----------------------
__global__ void ln_k(const float* __restrict__ in, float* __restrict__ out,
                     const float* __restrict__ w, const float* __restrict__ b,
                     float* __restrict__ zdbl, float* __restrict__ zxz)
{
    int row = blockIdx.x;
    int t = threadIdx.x;   // 128 threads
    if (zdbl != nullptr && t < DBL_N) zdbl[(size_t)row * DBL_N + t] = 0.f;
    if (zxz != nullptr) {
        float* zr = zxz + (size_t)row * (2 * D);
        #pragma unroll
        for (int q = 0; q < 6; q++) zr[t + q * 128] = 0.f;
    }
    const float* r = in + (size_t)row * D;
    float v0 = r[t], v1 = r[t + 128], v2 = r[t + 256];
    float s = v0 + v1 + v2;
    __shared__ float sh[4], sh2[4];
    #pragma unroll
    for (int o = 16; o; o >>= 1) s += __shfl_xor_sync(~0u, s, o);
    if ((t & 31) == 0) sh[t >> 5] = s;
    __syncthreads();
    float mu = (sh[0] + sh[1] + sh[2] + sh[3]) * (1.f / 384.f);
    float d0 = v0 - mu, d1 = v1 - mu, d2 = v2 - mu;
    float q = d0 * d0 + d1 * d1 + d2 * d2;
    #pragma unroll
    for (int o = 16; o; o >>= 1) q += __shfl_xor_sync(~0u, q, o);
    if ((t & 31) == 0) sh2[t >> 5] = q;
    __syncthreads();
    float var = (sh2[0] + sh2[1] + sh2[2] + sh2[3]) * (1.f / 384.f);
    float rs = rsqrtf(var + 1e-5f);
    float* o = out + (size_t)row * D;
    o[t]       = d0 * rs * w[t]       + b[t];
    o[t + 128] = d1 * rs * w[t + 128] + b[t + 128];
    o[t + 256] = d2 * rs * w[t + 256] + b[t + 256];
}

// ------------------------- positional embedding + patch bias ---------------
__global__ void posembed_k(const float* __restrict__ bp,
                           const unsigned char* __restrict__ mask,
                           const float* __restrict__ patch_b)
{
    int row = blockIdx.x;           // NTOK
    int d = threadIdx.x;            // 384
    int b = row >> 10, l = row & 1023;
    int gh = l >> 6, gw = (l >> 3) & 7, gd = l & 7;
    float vr = bp[b * 4 + 2];
    bool m = mask[b] != 0;
    int j = d / 128, r = d - j * 128, f = r & 63;
    float c;
    if (j == 0)      c = (float)gh * (1.f / 15.f);
    else if (j == 1) c = ((float)gw - 4.f) * 0.25f;
    else {
        float v = m ? ((float)gd - 4.f) * vr : (float)gd * vr;
        float den = m ? 4.f * vr : 7.f * vr;
        c = v / den;
    }
    float omega = powf(10000.f, -(float)f * (1.f / 64.f));
    float ph = c * omega;
    float pe = (r < 64) ? sinf(ph) : cosf(ph);
    g_tok[(size_t)row * D + d] += pe + patch_b[d];
}

// ------------------------- causal depthwise conv + silu --------------------
__global__ void conv_k(const float* __restrict__ cw, const float* __restrict__ cb)
{
    int row = blockIdx.x;           // NTOK
    int d = threadIdx.x;            // 384
    int l = row & 1023, b = row >> 10;
    float acc = cb[d];
    #pragma unroll
    for (int j = 0; j < 4; j++) {
        int ll = l - 3 + j;
        if (ll >= 0)
            acc = fmaf(g_xz[(size_t)((b << 10) + ll) * (2 * D) + d], cw[d * 4 + j], acc);
    }
    g_xc[(size_t)row * D + d] = acc / (1.f + __expf(-acc));
}

// ------------------------- chunked scan with inline dt_proj -----------------
// Grid (96, NCH). Block = 8 chains (d0..d0+7) x 16 lanes = 128 threads,
// ONE chunk of 128 steps. Full dbl rows staged; dt = softplus(dbl[:24] @ dtw
// + dtb) computed in-block (dt_proj GEMM eliminated).
struct ScanTilePart {
    __align__(16) float dbl[CHL][DBL_N];   // full row: [0:24) dt-rank, [24:56) B|C
    __align__(16) float xc[CHL][SCH];
    __align__(16) float dtw[DTRANK][SCH];
    __align__(16) float dt[CHL][SCH];
    float dtb[SCH];
};
struct ScanTileFull {
    __align__(16) float dbl[CHL][DBL_N];
    __align__(16) float xc[CHL][SCH];
    __align__(16) float dtw[DTRANK][SCH];
    __align__(16) float dt[CHL][SCH];
    __align__(16) float zz[CHL][SCH];
    __align__(16) float yy[CHL][SCH];
    float dtb[SCH];
};

// stage full dbl tile + xc tile + dtw slice + dtb
template <typename SM>
__device__ __forceinline__ void scan_stage(SM* sm, const float* dbl_b,
                                           const float* xc_g,
                                           const float* dtw, const float* dtb,
                                           int l0, int d0, int tid)
{
    uint32_t s_dbl = (uint32_t)__cvta_generic_to_shared(&sm->dbl[0][0]);
    uint32_t s_xc  = (uint32_t)__cvta_generic_to_shared(&sm->xc[0][0]);
    uint32_t s_dtw = (uint32_t)__cvta_generic_to_shared(&sm->dtw[0][0]);
    // dbl: 128 rows x 56 floats = 1792 x 16B
    #pragma unroll
    for (int q = 0; q < 14; q++) {
        int qq = tid + q * 128;
        int row = qq / 14, part = (qq % 14) << 2;
        cp_async16(s_dbl + (row * DBL_N + part) * 4,
                   dbl_b + (size_t)(l0 + row) * DBL_N + part, true);
    }
    // xc: 128 rows x 8 floats = 256 x 16B
    #pragma unroll
    for (int q = 0; q < 2; q++) {
        int qq = tid + q * 128;
        int row = qq >> 1, part = (qq & 1) << 2;
        cp_async16(s_xc + (row * SCH + part) * 4,
                   xc_g + (size_t)(l0 + row) * D + d0 + part, true);
    }
    // dtw: 24 rows x 8 floats = 48 x 16B
    if (tid < 48) {
        int r = tid >> 1, part = (tid & 1) << 2;
        cp_async16(s_dtw + (r * SCH + part) * 4,
                   dtw + (size_t)r * D + d0 + part, true);
    }
    if (tid < SCH) sm->dtb[tid] = __ldg(&dtb[d0 + tid]);
}

// compute dt rows from staged dbl (call after cp_wait + syncthreads)
template <typename SM>
__device__ __forceinline__ void scan_dt(SM* sm, int tid)
{
    float acc[SCH];
    #pragma unroll
    for (int j = 0; j < SCH; j++) acc[j] = sm->dtb[j];
    #pragma unroll
    for (int r = 0; r < DTRANK; r += 4) {
        float4 v = *reinterpret_cast<const float4*>(&sm->dbl[tid][r]);
        const float* vf = &v.x;
        #pragma unroll
        for (int c = 0; c < 4; c++)
            #pragma unroll
            for (int j = 0; j < SCH; j++)
                acc[j] = fmaf(vf[c], sm->dtw[r + c][j], acc[j]);
    }
    #pragma unroll
    for (int j = 0; j < SCH; j++)
        sm->dt[tid][j] = (acc[j] > 20.f) ? acc[j] : log1pf(__expf(acc[j]));
}

__global__ void scan_part_k(const float* __restrict__ A_log,
                            const float* __restrict__ dtw,
                            const float* __restrict__ dtb)
{
    __shared__ ScanTilePart sm;
    const int tid = threadIdx.x;
    const int grp = tid >> 4, lane = tid & 15;
    const int c = blockIdx.y;
    const int blk = blockIdx.x;             // 0..95
    const int b = blk / 48;
    const int d0 = (blk % 48) * SCH;
    const int d = d0 + grp;
    const int l0 = c * CHL;

    const float* dbl_b = g_dbl + (size_t)b * L * DBL_N;
    scan_stage(&sm, dbl_b, g_xc + (size_t)b * L * D, dtw, dtb, l0, d0, tid);
    cp_commit();

    const float Aa = -__expf(A_log[d * DSTATE + lane]);

    cp_wait<0>();
    __syncthreads();
    scan_dt(&sm, tid);
    __syncthreads();

    float h = 0.f, P = 1.f;
    #pragma unroll 8
    for (int l = 0; l < CHL; l++) {
        float dtv = sm.dt[l][grp];
        float uv  = sm.xc[l][grp];
        float Bv  = sm.dbl[l][DTRANK + lane];
        float dA  = __expf(dtv * Aa);
        h = fmaf(h, dA, dtv * uv * Bv);
        P *= dA;
    }
    const int chain = b * D + d;
    g_P[((size_t)chain * NCH + c) * DSTATE + lane] = P;
    g_W[((size_t)chain * NCH + c) * DSTATE + lane] = h;
}

__global__ void scan_full_k(const float* __restrict__ A_log,
                            const float* __restrict__ dtw,
                            const float* __restrict__ dtb,
                            const float* __restrict__ Dsk)
{
    __shared__ ScanTileFull sm;
    const int tid = threadIdx.x;
    const int grp = tid >> 4, lane = tid & 15;
    const int c = blockIdx.y;
    const int blk = blockIdx.x;             // 0..95
    const int b = blk / 48;
    const int d0 = (blk % 48) * SCH;
    const int d = d0 + grp;
    const int l0 = c * CHL;

    const float* dbl_b = g_dbl + (size_t)b * L * DBL_N;
    scan_stage(&sm, dbl_b, g_xc + (size_t)b * L * D, dtw, dtb, l0, d0, tid);
    {
        uint32_t s_zz = (uint32_t)__cvta_generic_to_shared(&sm.zz[0][0]);
        const float* z_g = g_xz + (size_t)b * L * (2 * D) + D;
        #pragma unroll
        for (int q = 0; q < 2; q++) {
            int qq = tid + q * 128;
            int row = qq >> 1, part = (qq & 1) << 2;
            cp_async16(s_zz + (row * SCH + part) * 4,
                       z_g + (size_t)(l0 + row) * (2 * D) + d0 + part, true);
        }
    }
    cp_commit();

    const float Aa = -__expf(A_log[d * DSTATE + lane]);
    const float Dp = __ldg(&Dsk[d]);
    const int chain = b * D + d;

    // prefix fold while tile loads
    float h = 0.f;
    const float* Pp = g_P + (size_t)chain * NCH * DSTATE + lane;
    const float* Wp = g_W + (size_t)chain * NCH * DSTATE + lane;
    for (int j = 0; j < c; j++)
        h = fmaf(h, Pp[(size_t)j * DSTATE], Wp[(size_t)j * DSTATE]);

    cp_wait<0>();
    __syncthreads();
    scan_dt(&sm, tid);
    __syncthreads();

    #pragma unroll 8
    for (int l = 0; l < CHL; l++) {
        float dtv = sm.dt[l][grp];
        float uv  = sm.xc[l][grp];
        float Bv  = sm.dbl[l][DTRANK + lane];
        float Cv  = sm.dbl[l][DTRANK + DSTATE + lane];
        float dA  = __expf(dtv * Aa);
        h = fmaf(h, dA, dtv * uv * Bv);
        float p = h * Cv;
        p += __shfl_xor_sync(0xffffffffu, p, 8);
        p += __shfl_xor_sync(0xffffffffu, p, 4);
        p += __shfl_xor_sync(0xffffffffu, p, 2);
        p += __shfl_xor_sync(0xffffffffu, p, 1);
        if (lane == 0) {
            float zv = sm.zz[l][grp];
            float sz = zv / (1.f + __expf(-zv));
            sm.yy[l][grp] = (p + uv * Dp) * sz;
        }
    }
    __syncthreads();

    float* y_g = g_y + (size_t)(b * L + l0 + tid) * D + d0;
    float4 v0 = *reinterpret_cast<const float4*>(&sm.yy[tid][0]);
    float4 v1 = *reinterpret_cast<const float4*>(&sm.yy[tid][4]);
    *reinterpret_cast<float4*>(y_g)     = v0;
    *reinterpret_cast<float4*>(y_g + 4) = v1;
}

// ------------------------- launch ------------------------------------------
extern "C" void kernel_launch(void* const* d_in, const int* in_sizes, int n_in,
                              void* d_out, int out_size)
{
    const float* x          = (const float*)d_in[0];
    const float* bp         = (const float*)d_in[1];
    const float* patch_w    = (const float*)d_in[2];
    const float* patch_b    = (const float*)d_in[3];
    const float* in_proj_w  = (const float*)d_in[4];
    const float* conv_w     = (const float*)d_in[5];
    const float* conv_b     = (const float*)d_in[6];
    const float* x_proj_w   = (const float*)d_in[7];
    const float* dt_proj_w  = (const float*)d_in[8];
    const float* dt_proj_b  = (const float*)d_in[9];
    const float* A_log      = (const float*)d_in[10];
    const float* Dskip      = (const float*)d_in[11];
    const float* out_proj_w = (const float*)d_in[12];
    const float* norm_w     = (const float*)d_in[13];
    const float* norm_b     = (const float*)d_in[14];
    const float* fw         = (const float*)d_in[15];
    const float* fb         = (const float*)d_in[16];
    const unsigned char* mask = (const unsigned char*)d_in[17];

    float *tok, *h, *xz, *xc, *dbl, *y;
    cudaGetSymbolAddress((void**)&tok, g_tok);
    cudaGetSymbolAddress((void**)&h,   g_h);
    cudaGetSymbolAddress((void**)&xz,  g_xz);
    cudaGetSymbolAddress((void**)&xc,  g_xc);
    cudaGetSymbolAddress((void**)&dbl, g_dbl);
    cudaGetSymbolAddress((void**)&y,   g_y);

    // patchify: zero tok, split-K=2 accumulate, bias+posembed fused
    zero_k<<<(NTOK * D + 255) / 256, 256>>>(tok, NTOK * D);
    sgemm_patch_k<<<dim3(D / 64, NTOK / 64, 2), 256>>>(x, patch_w, tok);
    posembed_k<<<NTOK, D>>>(bp, mask, patch_b);

    for (int layer = 0; layer < DEPTH; layer++) {
        ln_k<<<NTOK, 128>>>(tok, h, norm_w + layer * D, norm_b + layer * D, dbl, xz);
        sgemm_k<<<dim3((2 * D) / 64, NTOK / 64, 2), 256>>>(h, D,
                in_proj_w + (size_t)layer * D * 2 * D, xz, nullptr, NTOK, 2 * D, D, 0);
        conv_k<<<NTOK, D>>>(conv_w + (size_t)layer * D * 4, conv_b + (size_t)layer * D);
        sgemm_k<<<dim3(1, NTOK / 64, 6), 256>>>(xc, D,
                x_proj_w + (size_t)layer * D * DBL_N, dbl, nullptr, NTOK, DBL_N, D, 0);
        scan_part_k<<<dim3(96, NCH), 128>>>(A_log + (size_t)layer * D * DSTATE,
                                            dt_proj_w + (size_t)layer * DTRANK * D,
                                            dt_proj_b + (size_t)layer * D);
        scan_full_k<<<dim3(96, NCH), 128>>>(A_log + (size_t)layer * D * DSTATE,
                                            dt_proj_w + (size_t)layer * DTRANK * D,
                                            dt_proj_b + (size_t)layer * D,
                                            Dskip + (size_t)layer * D);
        sgemm_k<<<dim3(D / 64, NTOK / 64, 2), 256>>>(y, D,
                out_proj_w + (size_t)layer * D * D, tok, nullptr, NTOK, D, D, 3);
    }

    ln_k<<<NTOK, 128>>>(tok, (float*)d_out, fw, fb, nullptr, nullptr);
}

// round 13
// speedup vs baseline: 1.1535x; 1.1535x over previous
#include <cuda_runtime.h>
#include <math.h>
#include <stdint.h>

#define B_SZ 2
#define L 1024
#define D 384
#define PATCH_DIM 4096
#define DEPTH 12
#define DSTATE 16
#define DTRANK 24
#define DBL_N 56
#define NTOK (B_SZ * L)   // 2048
#define NCH 8             // scan chunks
#define CHL (L / NCH)     // 128 steps per chunk
#define SCH 8             // chains per scan block

typedef unsigned long long ull;

// ------------------------- scratch (static device) -------------------------
__device__ float g_tok[NTOK * D];
__device__ float g_h[NTOK * D];
__device__ float g_xz[NTOK * 2 * D];
__device__ float g_xc[NTOK * D];
__device__ float g_dbl[NTOK * DBL_N];
__device__ float g_dt[NTOK * D];
__device__ float g_y[NTOK * D];
__device__ float g_P[B_SZ * D * NCH * DSTATE];
__device__ float g_W[B_SZ * D * NCH * DSTATE];

// ------------------------- cp.async + f32x2 helpers ------------------------
__device__ __forceinline__ void cp_async16(uint32_t dst, const void* src, bool pred) {
    int sz = pred ? 16 : 0;
    asm volatile("cp.async.ca.shared.global [%0], [%1], 16, %2;\n"
                 :: "r"(dst), "l"(src), "r"(sz));
}
__device__ __forceinline__ void cp_commit() {
    asm volatile("cp.async.commit_group;\n");
}
template <int N>
__device__ __forceinline__ void cp_wait() {
    asm volatile("cp.async.wait_group %0;\n" :: "n"(N));
}
__device__ __forceinline__ ull pack2(float x, float y) {
    ull r; asm("mov.b64 %0, {%1, %2};" : "=l"(r) : "f"(x), "f"(y)); return r;
}
__device__ __forceinline__ void unpack2(ull v, float& x, float& y) {
    asm("mov.b64 {%0, %1}, %2;" : "=f"(x), "=f"(y) : "l"(v));
}
__device__ __forceinline__ void ffma2(ull& d, ull a, ull b) {
    asm("fma.rn.f32x2 %0, %1, %2, %0;" : "+l"(d) : "l"(a), "l"(b));
}

// ------------------------- pipelined SGEMM 64x64 (vector LDS + FFMA2) ------
#define BM 64
#define BN 64
#define BK 16
#define ASTRIDE 20

struct SmemGemm {
    __align__(16) float As[2][BM * ASTRIDE];
    __align__(16) float Bs[2][BK * BN];
};

__device__ __forceinline__ void gemm_inner(const float* __restrict__ As,
                                           const float* __restrict__ Bsr,
                                           int m0, int n0, ull acc2[4][2])
{
    #pragma unroll
    for (int k4 = 0; k4 < BK; k4 += 4) {
        float4 a[4];
        #pragma unroll
        for (int i = 0; i < 4; i++)
            a[i] = *reinterpret_cast<const float4*>(&As[(m0 + i) * ASTRIDE + k4]);
        #pragma unroll
        for (int q = 0; q < 4; q++) {
            float4 bq = *reinterpret_cast<const float4*>(&Bsr[(k4 + q) * BN + n0]);
            ull b01 = pack2(bq.x, bq.y);
            ull b23 = pack2(bq.z, bq.w);
            #pragma unroll
            for (int i = 0; i < 4; i++) {
                const float* af = &a[i].x;
                ull ap = pack2(af[q], af[q]);
                ffma2(acc2[i][0], ap, b01);
                ffma2(acc2[i][1], ap, b23);
            }
        }
    }
}

// epi: 0 none, 1 +bias, 2 +bias->softplus, 3 C += result.
// gridDim.z>1 -> split-K, partials accumulated via atomicAdd (bias ignored).
__global__ void sgemm_k(const float* __restrict__ A, int lda,
                        const float* __restrict__ Bm,
                        float* __restrict__ C,
                        const float* __restrict__ bias,
                        int M, int N, int K, int epi)
{
    __shared__ SmemGemm sm;
    const int bm = blockIdx.y * BM, bn = blockIdx.x * BN;
    const int tid = threadIdx.x;

    const int ksplit = gridDim.z;
    const int kc = K / ksplit;
    const int kstart = blockIdx.z * kc;
    const int kend = kstart + kc;
    const int niters = (kc + BK - 1) / BK;

    const int am  = tid >> 2;
    const int akq = (tid & 3) << 2;
    const int bkb = tid >> 4;
    const int bn4 = (tid & 15) << 2;
    const bool bn_ok = (bn + bn4) < N;

    const float* Arow = A + (size_t)(bm + am) * lda;

    uint32_t sAs = (uint32_t)__cvta_generic_to_shared(&sm.As[0][0]);
    uint32_t sBs = (uint32_t)__cvta_generic_to_shared(&sm.Bs[0][0]);

    auto load_stage = [&](int it, int buf) {
        int k0 = kstart + it * BK;
        {
            int k = k0 + akq;
            bool p = k < kend;
            const float* src = p ? (Arow + k) : A;
            cp_async16(sAs + (buf * BM * ASTRIDE + am * ASTRIDE + akq) * 4, src, p);
        }
        {
            int k = k0 + bkb;
            bool p = (k < kend) && bn_ok;
            const float* src = p ? (Bm + (size_t)k * N + bn + bn4) : Bm;
            cp_async16(sBs + (buf * BK * BN + bkb * BN + bn4) * 4, src, p);
        }
    };

    const int ty = tid >> 4, tx = tid & 15;
    const int m0 = ty * 4, n0 = tx * 4;

    ull acc2[4][2];
    #pragma unroll
    for (int i = 0; i < 4; i++) { acc2[i][0] = 0ull; acc2[i][1] = 0ull; }

    load_stage(0, 0); cp_commit();
    if (niters > 1) load_stage(1, 1);
    cp_commit();

    for (int it = 0; it < niters; it++) {
        cp_wait<1>();
        __syncthreads();
        const int buf = it & 1;
        gemm_inner(&sm.As[buf][0], &sm.Bs[buf][0], m0, n0, acc2);
        __syncthreads();
        if (it + 2 < niters) load_stage(it + 2, buf);
        cp_commit();
    }

    #pragma unroll
    for (int i = 0; i < 4; i++) {
        int row = bm + m0 + i;
        float v[4];
        unpack2(acc2[i][0], v[0], v[1]);
        unpack2(acc2[i][1], v[2], v[3]);
        #pragma unroll
        for (int j = 0; j < 4; j++) {
            int col = bn + n0 + j;
            if (col < N) {
                size_t off = (size_t)row * N + col;
                float vv = v[j];
                if (ksplit > 1) {
                    atomicAdd(&C[off], vv);
                } else {
                    if (epi == 1 || epi == 2) vv += bias[col];
                    if (epi == 2) vv = (vv > 20.f) ? vv : log1pf(__expf(vv));
                    if (epi == 3) vv += C[off];
                    C[off] = vv;
                }
            }
        }
    }
}

// ------------------------- patchify GEMM (im2col fused, split-K) -----------
__global__ void sgemm_patch_k(const float* __restrict__ X,
                              const float* __restrict__ Bm,
                              float* __restrict__ C)
{
    __shared__ SmemGemm sm;
    const int bm = blockIdx.y * BM, bn = blockIdx.x * BN;
    const int tid = threadIdx.x;
    const int N = D;

    const int kc = PATCH_DIM / gridDim.z;
    const int kstart = blockIdx.z * kc;
    const int niters = kc / BK;

    const int am  = tid >> 2;
    const int akq = (tid & 3) << 2;
    const int bkb = tid >> 4;
    const int bn4 = (tid & 15) << 2;

    const int m = bm + am;
    const int b = m >> 10, l = m & 1023;
    const int gh = l >> 6, gw = (l >> 3) & 7, gd = l & 7;
    const size_t xbase = ((size_t)(b * 256 + gh * 16) * 256 + gw * 32) * 64 + gd * 8;

    uint32_t sAs = (uint32_t)__cvta_generic_to_shared(&sm.As[0][0]);
    uint32_t sBs = (uint32_t)__cvta_generic_to_shared(&sm.Bs[0][0]);

    auto load_stage = [&](int it, int buf) {
        int k0 = kstart + it * BK;
        {
            int k = k0 + akq;
            int ph = k >> 8, pw = (k >> 3) & 31, pd = k & 7;
            const float* src = X + xbase + (size_t)ph * 16384 + pw * 64 + pd;
            cp_async16(sAs + (buf * BM * ASTRIDE + am * ASTRIDE + akq) * 4, src, true);
        }
        {
            int k = k0 + bkb;
            const float* src = Bm + (size_t)k * N + bn + bn4;
            cp_async16(sBs + (buf * BK * BN + bkb * BN + bn4) * 4, src, true);
        }
    };

    const int ty = tid >> 4, tx = tid & 15;
    const int m0 = ty * 4, n0 = tx * 4;

    ull acc2[4][2];
    #pragma unroll
    for (int i = 0; i < 4; i++) { acc2[i][0] = 0ull; acc2[i][1] = 0ull; }

    load_stage(0, 0); cp_commit();
    load_stage(1, 1); cp_commit();

    for (int it = 0; it < niters; it++) {
        cp_wait<1>();
        __syncthreads();
        const int buf = it & 1;
        gemm_inner(&sm.As[buf][0], &sm.Bs[buf][0], m0, n0, acc2);
        __syncthreads();
        if (it + 2 < niters) load_stage(it + 2, buf);
        cp_commit();
    }

    #pragma unroll
    for (int i = 0; i < 4; i++) {
        int row = bm + m0 + i;
        float v[4];
        unpack2(acc2[i][0], v[0], v[1]);
        unpack2(acc2[i][1], v[2], v[3]);
        #pragma unroll
        for (int j = 0; j < 4; j++)
            atomicAdd(&C[(size_t)row * N + bn + n0 + j], v[j]);
    }
}

// ------------------------- zero buffer --------------------------------------
__global__ void zero_k(float* __restrict__ p, int n) {
    int i = blockIdx.x * blockDim.x + threadIdx.x;
    if (i < n) p[i] = 0.f;
}

// ------------------------- LayerNorm + xz/dbl zeroing ----------------------
__global__ void ln_k(const float* __restrict__ in, float* __restrict__ out,
                     const float* __restrict__ w, const float* __restrict__ b,
                     float* __restrict__ zdbl, float* __restrict__ zxz)
{
    int row = blockIdx.x;
    int t = threadIdx.x;   // 128 threads
    if (zdbl != nullptr && t < DBL_N) zdbl[(size_t)row * DBL_N + t] = 0.f;
    if (zxz != nullptr) {
        float* zr = zxz + (size_t)row * (2 * D);
        #pragma unroll
        for (int q = 0; q < 6; q++) zr[t + q * 128] = 0.f;
    }
    const float* r = in + (size_t)row * D;
    float v0 = r[t], v1 = r[t + 128], v2 = r[t + 256];
    float s = v0 + v1 + v2;
    __shared__ float sh[4], sh2[4];
    #pragma unroll
    for (int o = 16; o; o >>= 1) s += __shfl_xor_sync(~0u, s, o);
    if ((t & 31) == 0) sh[t >> 5] = s;
    __syncthreads();
    float mu = (sh[0] + sh[1] + sh[2] + sh[3]) * (1.f / 384.f);
    float d0 = v0 - mu, d1 = v1 - mu, d2 = v2 - mu;
    float q = d0 * d0 + d1 * d1 + d2 * d2;
    #pragma unroll
    for (int o = 16; o; o >>= 1) q += __shfl_xor_sync(~0u, q, o);
    if ((t & 31) == 0) sh2[t >> 5] = q;
    __syncthreads();
    float var = (sh2[0] + sh2[1] + sh2[2] + sh2[3]) * (1.f / 384.f);
    float rs = rsqrtf(var + 1e-5f);
    float* o = out + (size_t)row * D;
    o[t]       = d0 * rs * w[t]       + b[t];
    o[t + 128] = d1 * rs * w[t + 128] + b[t + 128];
    o[t + 256] = d2 * rs * w[t + 256] + b[t + 256];
}

// ------------------------- positional embedding + patch bias ---------------
__global__ void posembed_k(const float* __restrict__ bp,
                           const unsigned char* __restrict__ mask,
                           const float* __restrict__ patch_b)
{
    int row = blockIdx.x;           // NTOK
    int d = threadIdx.x;            // 384
    int b = row >> 10, l = row & 1023;
    int gh = l >> 6, gw = (l >> 3) & 7, gd = l & 7;
    float vr = bp[b * 4 + 2];
    bool m = mask[b] != 0;
    int j = d / 128, r = d - j * 128, f = r & 63;
    float c;
    if (j == 0)      c = (float)gh * (1.f / 15.f);
    else if (j == 1) c = ((float)gw - 4.f) * 0.25f;
    else {
        float v = m ? ((float)gd - 4.f) * vr : (float)gd * vr;
        float den = m ? 4.f * vr : 7.f * vr;
        c = v / den;
    }
    float omega = powf(10000.f, -(float)f * (1.f / 64.f));
    float ph = c * omega;
    float pe = (r < 64) ? sinf(ph) : cosf(ph);
    g_tok[(size_t)row * D + d] += pe + patch_b[d];
}

// ------------------------- causal depthwise conv + silu --------------------
__global__ void conv_k(const float* __restrict__ cw, const float* __restrict__ cb)
{
    int row = blockIdx.x;           // NTOK
    int d = threadIdx.x;            // 384
    int l = row & 1023, b = row >> 10;
    float acc = cb[d];
    #pragma unroll
    for (int j = 0; j < 4; j++) {
        int ll = l - 3 + j;
        if (ll >= 0)
            acc = fmaf(g_xz[(size_t)((b << 10) + ll) * (2 * D) + d], cw[d * 4 + j], acc);
    }
    g_xc[(size_t)row * D + d] = acc / (1.f + __expf(-acc));
}

// ------------------------- chunked scan, smem-staged (R11 proven) ----------
struct ScanTilePart {
    __align__(16) float dt[CHL][SCH];
    __align__(16) float xc[CHL][SCH];
    __align__(16) float bc[CHL][32];   // B[16] | C[16]
};
struct ScanTileFull {
    __align__(16) float dt[CHL][SCH];
    __align__(16) float xc[CHL][SCH];
    __align__(16) float bc[CHL][32];
    __align__(16) float zz[CHL][SCH];
    __align__(16) float yy[CHL][SCH];
};

__device__ __forceinline__ void scan_load_common(
    uint32_t s_dt, uint32_t s_xc, uint32_t s_bc,
    const float* dt_g, const float* xc_g, const float* dbl_b,
    int l0, int d0, int tid)
{
    #pragma unroll
    for (int q = 0; q < 2; q++) {
        int qq = tid + q * 128;
        int row = qq >> 1, part = (qq & 1) << 2;
        cp_async16(s_dt + (row * SCH + part) * 4,
                   dt_g + (size_t)(l0 + row) * D + d0 + part, true);
        cp_async16(s_xc + (row * SCH + part) * 4,
                   xc_g + (size_t)(l0 + row) * D + d0 + part, true);
    }
    #pragma unroll
    for (int q = 0; q < 8; q++) {
        int qq = tid + q * 128;
        int row = qq >> 3, part = (qq & 7) << 2;
        cp_async16(s_bc + (row * 32 + part) * 4,
                   dbl_b + (size_t)(l0 + row) * DBL_N + DTRANK + part, true);
    }
}

__global__ void scan_part_k(const float* __restrict__ A_log)
{
    __shared__ ScanTilePart sm;
    const int tid = threadIdx.x;
    const int grp = tid >> 4, lane = tid & 15;
    const int c = blockIdx.y;
    const int blk = blockIdx.x;             // 0..95
    const int b = blk / 48;
    const int d0 = (blk % 48) * SCH;
    const int d = d0 + grp;
    const int l0 = c * CHL;

    const float* dbl_b = g_dbl + (size_t)b * L * DBL_N;
    scan_load_common((uint32_t)__cvta_generic_to_shared(&sm.dt[0][0]),
                     (uint32_t)__cvta_generic_to_shared(&sm.xc[0][0]),
                     (uint32_t)__cvta_generic_to_shared(&sm.bc[0][0]),
                     g_dt + (size_t)b * L * D, g_xc + (size_t)b * L * D,
                     dbl_b, l0, d0, tid);
    cp_commit();

    const float Aa = -__expf(A_log[d * DSTATE + lane]);

    cp_wait<0>();
    __syncthreads();

    float h = 0.f, P = 1.f;
    #pragma unroll 8
    for (int l = 0; l < CHL; l++) {
        float dtv = sm.dt[l][grp];
        float uv  = sm.xc[l][grp];
        float Bv  = sm.bc[l][lane];
        float dA  = __expf(dtv * Aa);
        h = fmaf(h, dA, dtv * uv * Bv);
        P *= dA;
    }
    const int chain = b * D + d;
    g_P[((size_t)chain * NCH + c) * DSTATE + lane] = P;
    g_W[((size_t)chain * NCH + c) * DSTATE + lane] = h;
}

__global__ void scan_full_k(const float* __restrict__ A_log,
                            const float* __restrict__ Dsk)
{
    __shared__ ScanTileFull sm;
    const int tid = threadIdx.x;
    const int grp = tid >> 4, lane = tid & 15;
    const int c = blockIdx.y;
    const int blk = blockIdx.x;             // 0..95
    const int b = blk / 48;
    const int d0 = (blk % 48) * SCH;
    const int d = d0 + grp;
    const int l0 = c * CHL;

    const float* dbl_b = g_dbl + (size_t)b * L * DBL_N;
    scan_load_common((uint32_t)__cvta_generic_to_shared(&sm.dt[0][0]),
                     (uint32_t)__cvta_generic_to_shared(&sm.xc[0][0]),
                     (uint32_t)__cvta_generic_to_shared(&sm.bc[0][0]),
                     g_dt + (size_t)b * L * D, g_xc + (size_t)b * L * D,
                     dbl_b, l0, d0, tid);
    {
        uint32_t s_zz = (uint32_t)__cvta_generic_to_shared(&sm.zz[0][0]);
        const float* z_g = g_xz + (size_t)b * L * (2 * D) + D;
        #pragma unroll
        for (int q = 0; q < 2; q++) {
            int qq = tid + q * 128;
            int row = qq >> 1, part = (qq & 1) << 2;
            cp_async16(s_zz + (row * SCH + part) * 4,
                       z_g + (size_t)(l0 + row) * (2 * D) + d0 + part, true);
        }
    }
    cp_commit();

    const float Aa = -__expf(A_log[d * DSTATE + lane]);
    const float Dp = __ldg(&Dsk[d]);
    const int chain = b * D + d;

    float h = 0.f;
    const float* Pp = g_P + (size_t)chain * NCH * DSTATE + lane;
    const float* Wp = g_W + (size_t)chain * NCH * DSTATE + lane;
    for (int j = 0; j < c; j++)
        h = fmaf(h, Pp[(size_t)j * DSTATE], Wp[(size_t)j * DSTATE]);

    cp_wait<0>();
    __syncthreads();

    #pragma unroll 8
    for (int l = 0; l < CHL; l++) {
        float dtv = sm.dt[l][grp];
        float uv  = sm.xc[l][grp];
        float Bv  = sm.bc[l][lane];
        float Cv  = sm.bc[l][lane + 16];
        float dA  = __expf(dtv * Aa);
        h = fmaf(h, dA, dtv * uv * Bv);
        float p = h * Cv;
        p += __shfl_xor_sync(0xffffffffu, p, 8);
        p += __shfl_xor_sync(0xffffffffu, p, 4);
        p += __shfl_xor_sync(0xffffffffu, p, 2);
        p += __shfl_xor_sync(0xffffffffu, p, 1);
        if (lane == 0) {
            float zv = sm.zz[l][grp];
            float sz = zv / (1.f + __expf(-zv));
            sm.yy[l][grp] = (p + uv * Dp) * sz;
        }
    }
    __syncthreads();

    float* y_g = g_y + (size_t)(b * L + l0 + tid) * D + d0;
    float4 v0 = *reinterpret_cast<const float4*>(&sm.yy[tid][0]);
    float4 v1 = *reinterpret_cast<const float4*>(&sm.yy[tid][4]);
    *reinterpret_cast<float4*>(y_g)     = v0;
    *reinterpret_cast<float4*>(y_g + 4) = v1;
}

// ------------------------- launch ------------------------------------------
extern "C" void kernel_launch(void* const* d_in, const int* in_sizes, int n_in,
                              void* d_out, int out_size)
{
    const float* x          = (const float*)d_in[0];
    const float* bp         = (const float*)d_in[1];
    const float* patch_w    = (const float*)d_in[2];
    const float* patch_b    = (const float*)d_in[3];
    const float* in_proj_w  = (const float*)d_in[4];
    const float* conv_w     = (const float*)d_in[5];
    const float* conv_b     = (const float*)d_in[6];
    const float* x_proj_w   = (const float*)d_in[7];
    const float* dt_proj_w  = (const float*)d_in[8];
    const float* dt_proj_b  = (const float*)d_in[9];
    const float* A_log      = (const float*)d_in[10];
    const float* Dskip      = (const float*)d_in[11];
    const float* out_proj_w = (const float*)d_in[12];
    const float* norm_w     = (const float*)d_in[13];
    const float* norm_b     = (const float*)d_in[14];
    const float* fw         = (const float*)d_in[15];
    const float* fb         = (const float*)d_in[16];
    const unsigned char* mask = (const unsigned char*)d_in[17];

    float *tok, *h, *xz, *xc, *dbl, *dt, *y;
    cudaGetSymbolAddress((void**)&tok, g_tok);
    cudaGetSymbolAddress((void**)&h,   g_h);
    cudaGetSymbolAddress((void**)&xz,  g_xz);
    cudaGetSymbolAddress((void**)&xc,  g_xc);
    cudaGetSymbolAddress((void**)&dbl, g_dbl);
    cudaGetSymbolAddress((void**)&dt,  g_dt);
    cudaGetSymbolAddress((void**)&y,   g_y);

    // patchify: zero tok, split-K=4 accumulate, bias+posembed fused
    zero_k<<<(NTOK * D + 255) / 256, 256>>>(tok, NTOK * D);
    sgemm_patch_k<<<dim3(D / 64, NTOK / 64, 4), 256>>>(x, patch_w, tok);
    posembed_k<<<NTOK, D>>>(bp, mask, patch_b);

    for (int layer = 0; layer < DEPTH; layer++) {
        ln_k<<<NTOK, 128>>>(tok, h, norm_w + layer * D, norm_b + layer * D, dbl, xz);
        sgemm_k<<<dim3((2 * D) / 64, NTOK / 64, 3), 256>>>(h, D,
                in_proj_w + (size_t)layer * D * 2 * D, xz, nullptr, NTOK, 2 * D, D, 0);
        conv_k<<<NTOK, D>>>(conv_w + (size_t)layer * D * 4, conv_b + (size_t)layer * D);
        sgemm_k<<<dim3(1, NTOK / 64, 4), 256>>>(xc, D,
                x_proj_w + (size_t)layer * D * DBL_N, dbl, nullptr, NTOK, DBL_N, D, 0);
        sgemm_k<<<dim3(D / 64, NTOK / 64, 1), 256>>>(dbl, DBL_N,
                dt_proj_w + (size_t)layer * DTRANK * D, dt, dt_proj_b + (size_t)layer * D,
                NTOK, D, DTRANK, 2);
        scan_part_k<<<dim3(96, NCH), 128>>>(A_log + (size_t)layer * D * DSTATE);
        scan_full_k<<<dim3(96, NCH), 128>>>(A_log + (size_t)layer * D * DSTATE,
                                            Dskip + (size_t)layer * D);
        // out_proj: split-K=3, atomicAdd accumulates residual into tok directly
        sgemm_k<<<dim3(D / 64, NTOK / 64, 3), 256>>>(y, D,
                out_proj_w + (size_t)layer * D * D, tok, nullptr, NTOK, D, D, 3);
    }

    ln_k<<<NTOK, 128>>>(tok, (float*)d_out, fw, fb, nullptr, nullptr);
}

// round 14
// speedup vs baseline: 1.1702x; 1.0144x over previous
#include <cuda_runtime.h>
#include <math.h>
#include <stdint.h>

#define B_SZ 2
#define L 1024
#define D 384
#define PATCH_DIM 4096
#define DEPTH 12
#define DSTATE 16
#define DTRANK 24
#define DBL_N 56
#define NTOK (B_SZ * L)   // 2048
#define NCH 8             // scan chunks
#define CHL (L / NCH)     // 128 steps per chunk
#define SCH 8             // chains per scan block

typedef unsigned long long ull;

// ------------------------- scratch (static device) -------------------------
__device__ float g_tok[NTOK * D];
__device__ float g_h[NTOK * D];
__device__ float g_xz[NTOK * 2 * D];
__device__ float g_xc[NTOK * D];
__device__ float g_dbl[NTOK * DBL_N];
__device__ float g_dt[NTOK * D];
__device__ float g_y[NTOK * D];
__device__ float g_P[B_SZ * D * NCH * DSTATE];
__device__ float g_W[B_SZ * D * NCH * DSTATE];

// ------------------------- cp.async + f32x2 helpers ------------------------
__device__ __forceinline__ void cp_async16(uint32_t dst, const void* src, bool pred) {
    int sz = pred ? 16 : 0;
    asm volatile("cp.async.ca.shared.global [%0], [%1], 16, %2;\n"
                 :: "r"(dst), "l"(src), "r"(sz));
}
__device__ __forceinline__ void cp_commit() {
    asm volatile("cp.async.commit_group;\n");
}
template <int N>
__device__ __forceinline__ void cp_wait() {
    asm volatile("cp.async.wait_group %0;\n" :: "n"(N));
}
__device__ __forceinline__ ull pack2(float x, float y) {
    ull r; asm("mov.b64 %0, {%1, %2};" : "=l"(r) : "f"(x), "f"(y)); return r;
}
__device__ __forceinline__ void unpack2(ull v, float& x, float& y) {
    asm("mov.b64 {%0, %1}, %2;" : "=f"(x), "=f"(y) : "l"(v));
}
__device__ __forceinline__ void ffma2(ull& d, ull a, ull b) {
    asm("fma.rn.f32x2 %0, %1, %2, %0;" : "+l"(d) : "l"(a), "l"(b));
}

// ------------------------- pipelined SGEMM 64x64 (vector LDS + FFMA2) ------
#define BM 64
#define BN 64
#define BK 16
#define ASTRIDE 20

struct SmemGemm {
    __align__(16) float As[2][BM * ASTRIDE];
    __align__(16) float Bs[2][BK * BN];
};

__device__ __forceinline__ void gemm_inner(const float* __restrict__ As,
                                           const float* __restrict__ Bsr,
                                           int m0, int n0, ull acc2[4][2])
{
    #pragma unroll
    for (int k4 = 0; k4 < BK; k4 += 4) {
        float4 a[4];
        #pragma unroll
        for (int i = 0; i < 4; i++)
            a[i] = *reinterpret_cast<const float4*>(&As[(m0 + i) * ASTRIDE + k4]);
        #pragma unroll
        for (int q = 0; q < 4; q++) {
            float4 bq = *reinterpret_cast<const float4*>(&Bsr[(k4 + q) * BN + n0]);
            ull b01 = pack2(bq.x, bq.y);
            ull b23 = pack2(bq.z, bq.w);
            #pragma unroll
            for (int i = 0; i < 4; i++) {
                const float* af = &a[i].x;
                ull ap = pack2(af[q], af[q]);
                ffma2(acc2[i][0], ap, b01);
                ffma2(acc2[i][1], ap, b23);
            }
        }
    }
}

// epi: 0 none, 1 +bias, 3 C += result.
// gridDim.z>1 -> split-K, partials accumulated via atomicAdd (bias ignored).
__global__ void sgemm_k(const float* __restrict__ A, int lda,
                        const float* __restrict__ Bm,
                        float* __restrict__ C,
                        const float* __restrict__ bias,
                        int M, int N, int K, int epi)
{
    __shared__ SmemGemm sm;
    const int bm = blockIdx.y * BM, bn = blockIdx.x * BN;
    const int tid = threadIdx.x;

    const int ksplit = gridDim.z;
    const int kc = K / ksplit;
    const int kstart = blockIdx.z * kc;
    const int kend = kstart + kc;
    const int niters = (kc + BK - 1) / BK;

    const int am  = tid >> 2;
    const int akq = (tid & 3) << 2;
    const int bkb = tid >> 4;
    const int bn4 = (tid & 15) << 2;
    const bool bn_ok = (bn + bn4) < N;

    const float* Arow = A + (size_t)(bm + am) * lda;

    uint32_t sAs = (uint32_t)__cvta_generic_to_shared(&sm.As[0][0]);
    uint32_t sBs = (uint32_t)__cvta_generic_to_shared(&sm.Bs[0][0]);

    auto load_stage = [&](int it, int buf) {
        int k0 = kstart + it * BK;
        {
            int k = k0 + akq;
            bool p = k < kend;
            const float* src = p ? (Arow + k) : A;
            cp_async16(sAs + (buf * BM * ASTRIDE + am * ASTRIDE + akq) * 4, src, p);
        }
        {
            int k = k0 + bkb;
            bool p = (k < kend) && bn_ok;
            const float* src = p ? (Bm + (size_t)k * N + bn + bn4) : Bm;
            cp_async16(sBs + (buf * BK * BN + bkb * BN + bn4) * 4, src, p);
        }
    };

    const int ty = tid >> 4, tx = tid & 15;
    const int m0 = ty * 4, n0 = tx * 4;

    ull acc2[4][2];
    #pragma unroll
    for (int i = 0; i < 4; i++) { acc2[i][0] = 0ull; acc2[i][1] = 0ull; }

    load_stage(0, 0); cp_commit();
    if (niters > 1) load_stage(1, 1);
    cp_commit();

    for (int it = 0; it < niters; it++) {
        cp_wait<1>();
        __syncthreads();
        const int buf = it & 1;
        gemm_inner(&sm.As[buf][0], &sm.Bs[buf][0], m0, n0, acc2);
        __syncthreads();
        if (it + 2 < niters) load_stage(it + 2, buf);
        cp_commit();
    }

    #pragma unroll
    for (int i = 0; i < 4; i++) {
        int row = bm + m0 + i;
        float v[4];
        unpack2(acc2[i][0], v[0], v[1]);
        unpack2(acc2[i][1], v[2], v[3]);
        #pragma unroll
        for (int j = 0; j < 4; j++) {
            int col = bn + n0 + j;
            if (col < N) {
                size_t off = (size_t)row * N + col;
                float vv = v[j];
                if (ksplit > 1) {
                    atomicAdd(&C[off], vv);
                } else {
                    if (epi == 1) vv += bias[col];
                    if (epi == 3) vv += C[off];
                    C[off] = vv;
                }
            }
        }
    }
}

// ------------------------- patchify GEMM (im2col fused, split-K) -----------
__global__ void sgemm_patch_k(const float* __restrict__ X,
                              const float* __restrict__ Bm,
                              float* __restrict__ C)
{
    __shared__ SmemGemm sm;
    const int bm = blockIdx.y * BM, bn = blockIdx.x * BN;
    const int tid = threadIdx.x;
    const int N = D;

    const int kc = PATCH_DIM / gridDim.z;
    const int kstart = blockIdx.z * kc;
    const int niters = kc / BK;

    const int am  = tid >> 2;
    const int akq = (tid & 3) << 2;
    const int bkb = tid >> 4;
    const int bn4 = (tid & 15) << 2;

    const int m = bm + am;
    const int b = m >> 10, l = m & 1023;
    const int gh = l >> 6, gw = (l >> 3) & 7, gd = l & 7;
    const size_t xbase = ((size_t)(b * 256 + gh * 16) * 256 + gw * 32) * 64 + gd * 8;

    uint32_t sAs = (uint32_t)__cvta_generic_to_shared(&sm.As[0][0]);
    uint32_t sBs = (uint32_t)__cvta_generic_to_shared(&sm.Bs[0][0]);

    auto load_stage = [&](int it, int buf) {
        int k0 = kstart + it * BK;
        {
            int k = k0 + akq;
            int ph = k >> 8, pw = (k >> 3) & 31, pd = k & 7;
            const float* src = X + xbase + (size_t)ph * 16384 + pw * 64 + pd;
            cp_async16(sAs + (buf * BM * ASTRIDE + am * ASTRIDE + akq) * 4, src, true);
        }
        {
            int k = k0 + bkb;
            const float* src = Bm + (size_t)k * N + bn + bn4;
            cp_async16(sBs + (buf * BK * BN + bkb * BN + bn4) * 4, src, true);
        }
    };

    const int ty = tid >> 4, tx = tid & 15;
    const int m0 = ty * 4, n0 = tx * 4;

    ull acc2[4][2];
    #pragma unroll
    for (int i = 0; i < 4; i++) { acc2[i][0] = 0ull; acc2[i][1] = 0ull; }

    load_stage(0, 0); cp_commit();
    load_stage(1, 1); cp_commit();

    for (int it = 0; it < niters; it++) {
        cp_wait<1>();
        __syncthreads();
        const int buf = it & 1;
        gemm_inner(&sm.As[buf][0], &sm.Bs[buf][0], m0, n0, acc2);
        __syncthreads();
        if (it + 2 < niters) load_stage(it + 2, buf);
        cp_commit();
    }

    #pragma unroll
    for (int i = 0; i < 4; i++) {
        int row = bm + m0 + i;
        float v[4];
        unpack2(acc2[i][0], v[0], v[1]);
        unpack2(acc2[i][1], v[2], v[3]);
        #pragma unroll
        for (int j = 0; j < 4; j++)
            atomicAdd(&C[(size_t)row * N + bn + n0 + j], v[j]);
    }
}

// ------------------------- zero buffer --------------------------------------
__global__ void zero_k(float* __restrict__ p, int n) {
    int i = blockIdx.x * blockDim.x + threadIdx.x;
    if (i < n) p[i] = 0.f;
}

// ------------------------- LayerNorm + xz/dbl zeroing ----------------------
__global__ void ln_k(const float* __restrict__ in, float* __restrict__ out,
                     const float* __restrict__ w, const float* __restrict__ b,
                     float* __restrict__ zdbl, float* __restrict__ zxz)
{
    int row = blockIdx.x;
    int t = threadIdx.x;   // 128 threads
    if (zdbl != nullptr && t < DBL_N) zdbl[(size_t)row * DBL_N + t] = 0.f;
    if (zxz != nullptr) {
        float* zr = zxz + (size_t)row * (2 * D);
        #pragma unroll
        for (int q = 0; q < 6; q++) zr[t + q * 128] = 0.f;
    }
    const float* r = in + (size_t)row * D;
    float v0 = r[t], v1 = r[t + 128], v2 = r[t + 256];
    float s = v0 + v1 + v2;
    __shared__ float sh[4], sh2[4];
    #pragma unroll
    for (int o = 16; o; o >>= 1) s += __shfl_xor_sync(~0u, s, o);
    if ((t & 31) == 0) sh[t >> 5] = s;
    __syncthreads();
    float mu = (sh[0] + sh[1] + sh[2] + sh[3]) * (1.f / 384.f);
    float d0 = v0 - mu, d1 = v1 - mu, d2 = v2 - mu;
    float q = d0 * d0 + d1 * d1 + d2 * d2;
    #pragma unroll
    for (int o = 16; o; o >>= 1) q += __shfl_xor_sync(~0u, q, o);
    if ((t & 31) == 0) sh2[t >> 5] = q;
    __syncthreads();
    float var = (sh2[0] + sh2[1] + sh2[2] + sh2[3]) * (1.f / 384.f);
    float rs = rsqrtf(var + 1e-5f);
    float* o = out + (size_t)row * D;
    o[t]       = d0 * rs * w[t]       + b[t];
    o[t + 128] = d1 * rs * w[t + 128] + b[t + 128];
    o[t + 256] = d2 * rs * w[t + 256] + b[t + 256];
}

// ------------------------- positional embedding + patch bias ---------------
__global__ void posembed_k(const float* __restrict__ bp,
                           const unsigned char* __restrict__ mask,
                           const float* __restrict__ patch_b)
{
    int row = blockIdx.x;           // NTOK
    int d = threadIdx.x;            // 384
    int b = row >> 10, l = row & 1023;
    int gh = l >> 6, gw = (l >> 3) & 7, gd = l & 7;
    float vr = bp[b * 4 + 2];
    bool m = mask[b] != 0;
    int j = d / 128, r = d - j * 128, f = r & 63;
    float c;
    if (j == 0)      c = (float)gh * (1.f / 15.f);
    else if (j == 1) c = ((float)gw - 4.f) * 0.25f;
    else {
        float v = m ? ((float)gd - 4.f) * vr : (float)gd * vr;
        float den = m ? 4.f * vr : 7.f * vr;
        c = v / den;
    }
    float omega = powf(10000.f, -(float)f * (1.f / 64.f));
    float ph = c * omega;
    float pe = (r < 64) ? sinf(ph) : cosf(ph);
    g_tok[(size_t)row * D + d] += pe + patch_b[d];
}

// ------------------------- causal depthwise conv + silu --------------------
__global__ void conv_k(const float* __restrict__ cw, const float* __restrict__ cb)
{
    int row = blockIdx.x;           // NTOK
    int d = threadIdx.x;            // 384
    int l = row & 1023, b = row >> 10;
    float acc = cb[d];
    #pragma unroll
    for (int j = 0; j < 4; j++) {
        int ll = l - 3 + j;
        if (ll >= 0)
            acc = fmaf(g_xz[(size_t)((b << 10) + ll) * (2 * D) + d], cw[d * 4 + j], acc);
    }
    g_xc[(size_t)row * D + d] = acc / (1.f + __expf(-acc));
}

// ------------------------- chunked scan, smem-staged ------------------------
// scan_part additionally computes dt = softplus(dbl[:, :24] @ dtw + dtb)
// (dt_proj GEMM eliminated) and writes it to g_dt for scan_full.
struct ScanTilePart {
    __align__(16) float dtr[CHL][DTRANK];  // dbl[:, 0:24]   12 KB
    __align__(16) float xc[CHL][SCH];      //                 4 KB
    __align__(16) float bc[CHL][32];       // B[16] | C[16]  16 KB
    __align__(16) float dt[CHL][SCH];      //                 4 KB
    __align__(16) float dtw[DTRANK][SCH];  //               768 B
    float dtb[SCH];
};
struct ScanTileFull {
    __align__(16) float dt[CHL][SCH];
    __align__(16) float xc[CHL][SCH];
    __align__(16) float bc[CHL][32];
    __align__(16) float zz[CHL][SCH];
    __align__(16) float yy[CHL][SCH];
};

__global__ void scan_part_k(const float* __restrict__ A_log,
                            const float* __restrict__ dtw,
                            const float* __restrict__ dtb)
{
    __shared__ ScanTilePart sm;
    const int tid = threadIdx.x;
    const int grp = tid >> 4, lane = tid & 15;
    const int c = blockIdx.y;
    const int blk = blockIdx.x;             // 0..95
    const int b = blk / 48;
    const int d0 = (blk % 48) * SCH;
    const int d = d0 + grp;
    const int l0 = c * CHL;

    const float* dbl_b = g_dbl + (size_t)b * L * DBL_N;
    const float* xc_g  = g_xc + (size_t)b * L * D;

    uint32_t s_dtr = (uint32_t)__cvta_generic_to_shared(&sm.dtr[0][0]);
    uint32_t s_xc  = (uint32_t)__cvta_generic_to_shared(&sm.xc[0][0]);
    uint32_t s_bc  = (uint32_t)__cvta_generic_to_shared(&sm.bc[0][0]);
    uint32_t s_dtw = (uint32_t)__cvta_generic_to_shared(&sm.dtw[0][0]);

    // dtr: 128 rows x 24 floats = 768 x 16B txns
    #pragma unroll
    for (int q = 0; q < 6; q++) {
        int qq = tid + q * 128;
        int row = qq / 6, part = (qq % 6) << 2;
        cp_async16(s_dtr + (row * DTRANK + part) * 4,
                   dbl_b + (size_t)(l0 + row) * DBL_N + part, true);
    }
    // xc: 256 txns
    #pragma unroll
    for (int q = 0; q < 2; q++) {
        int qq = tid + q * 128;
        int row = qq >> 1, part = (qq & 1) << 2;
        cp_async16(s_xc + (row * SCH + part) * 4,
                   xc_g + (size_t)(l0 + row) * D + d0 + part, true);
    }
    // bc: 1024 txns
    #pragma unroll
    for (int q = 0; q < 8; q++) {
        int qq = tid + q * 128;
        int row = qq >> 3, part = (qq & 7) << 2;
        cp_async16(s_bc + (row * 32 + part) * 4,
                   dbl_b + (size_t)(l0 + row) * DBL_N + DTRANK + part, true);
    }
    // dtw: 24 rows x 8 = 48 txns
    if (tid < 48) {
        int r = tid >> 1, part = (tid & 1) << 2;
        cp_async16(s_dtw + (r * SCH + part) * 4,
                   dtw + (size_t)r * D + d0 + part, true);
    }
    if (tid < SCH) sm.dtb[tid] = __ldg(&dtb[d0 + tid]);
    cp_commit();

    const float Aa = -__expf(A_log[d * DSTATE + lane]);

    cp_wait<0>();
    __syncthreads();

    // per-row dt compute (thread = row tid)
    {
        float acc[SCH];
        #pragma unroll
        for (int j = 0; j < SCH; j++) acc[j] = sm.dtb[j];
        #pragma unroll
        for (int r = 0; r < DTRANK; r += 4) {
            float4 v = *reinterpret_cast<const float4*>(&sm.dtr[tid][r]);
            const float* vf = &v.x;
            #pragma unroll
            for (int cc = 0; cc < 4; cc++)
                #pragma unroll
                for (int j = 0; j < SCH; j++)
                    acc[j] = fmaf(vf[cc], sm.dtw[r + cc][j], acc[j]);
        }
        #pragma unroll
        for (int j = 0; j < SCH; j++)
            acc[j] = (acc[j] > 20.f) ? acc[j] : log1pf(__expf(acc[j]));
        #pragma unroll
        for (int j = 0; j < SCH; j++) sm.dt[tid][j] = acc[j];
        // write dt to global for scan_full (coalesced STG.128 x2)
        float* dtg = g_dt + (size_t)(b * L + l0 + tid) * D + d0;
        *reinterpret_cast<float4*>(dtg)     = make_float4(acc[0], acc[1], acc[2], acc[3]);
        *reinterpret_cast<float4*>(dtg + 4) = make_float4(acc[4], acc[5], acc[6], acc[7]);
    }
    __syncthreads();

    float h = 0.f, P = 1.f;
    #pragma unroll 8
    for (int l = 0; l < CHL; l++) {
        float dtv = sm.dt[l][grp];
        float uv  = sm.xc[l][grp];
        float Bv  = sm.bc[l][lane];
        float dA  = __expf(dtv * Aa);
        h = fmaf(h, dA, dtv * uv * Bv);
        P *= dA;
    }
    const int chain = b * D + d;
    g_P[((size_t)chain * NCH + c) * DSTATE + lane] = P;
    g_W[((size_t)chain * NCH + c) * DSTATE + lane] = h;
}

__global__ void scan_full_k(const float* __restrict__ A_log,
                            const float* __restrict__ Dsk)
{
    __shared__ ScanTileFull sm;
    const int tid = threadIdx.x;
    const int grp = tid >> 4, lane = tid & 15;
    const int c = blockIdx.y;
    const int blk = blockIdx.x;             // 0..95
    const int b = blk / 48;
    const int d0 = (blk % 48) * SCH;
    const int d = d0 + grp;
    const int l0 = c * CHL;

    const float* dbl_b = g_dbl + (size_t)b * L * DBL_N;
    const float* dt_g  = g_dt + (size_t)b * L * D;
    const float* xc_g  = g_xc + (size_t)b * L * D;

    uint32_t s_dt = (uint32_t)__cvta_generic_to_shared(&sm.dt[0][0]);
    uint32_t s_xc = (uint32_t)__cvta_generic_to_shared(&sm.xc[0][0]);
    uint32_t s_bc = (uint32_t)__cvta_generic_to_shared(&sm.bc[0][0]);

    #pragma unroll
    for (int q = 0; q < 2; q++) {
        int qq = tid + q * 128;
        int row = qq >> 1, part = (qq & 1) << 2;
        cp_async16(s_dt + (row * SCH + part) * 4,
                   dt_g + (size_t)(l0 + row) * D + d0 + part, true);
        cp_async16(s_xc + (row * SCH + part) * 4,
                   xc_g + (size_t)(l0 + row) * D + d0 + part, true);
    }
    #pragma unroll
    for (int q = 0; q < 8; q++) {
        int qq = tid + q * 128;
        int row = qq >> 3, part = (qq & 7) << 2;
        cp_async16(s_bc + (row * 32 + part) * 4,
                   dbl_b + (size_t)(l0 + row) * DBL_N + DTRANK + part, true);
    }
    {
        uint32_t s_zz = (uint32_t)__cvta_generic_to_shared(&sm.zz[0][0]);
        const float* z_g = g_xz + (size_t)b * L * (2 * D) + D;
        #pragma unroll
        for (int q = 0; q < 2; q++) {
            int qq = tid + q * 128;
            int row = qq >> 1, part = (qq & 1) << 2;
            cp_async16(s_zz + (row * SCH + part) * 4,
                       z_g + (size_t)(l0 + row) * (2 * D) + d0 + part, true);
        }
    }
    cp_commit();

    const float Aa = -__expf(A_log[d * DSTATE + lane]);
    const float Dp = __ldg(&Dsk[d]);
    const int chain = b * D + d;

    float h = 0.f;
    const float* Pp = g_P + (size_t)chain * NCH * DSTATE + lane;
    const float* Wp = g_W + (size_t)chain * NCH * DSTATE + lane;
    for (int j = 0; j < c; j++)
        h = fmaf(h, Pp[(size_t)j * DSTATE], Wp[(size_t)j * DSTATE]);

    cp_wait<0>();
    __syncthreads();

    #pragma unroll 8
    for (int l = 0; l < CHL; l++) {
        float dtv = sm.dt[l][grp];
        float uv  = sm.xc[l][grp];
        float Bv  = sm.bc[l][lane];
        float Cv  = sm.bc[l][lane + 16];
        float dA  = __expf(dtv * Aa);
        h = fmaf(h, dA, dtv * uv * Bv);
        float p = h * Cv;
        p += __shfl_xor_sync(0xffffffffu, p, 8);
        p += __shfl_xor_sync(0xffffffffu, p, 4);
        p += __shfl_xor_sync(0xffffffffu, p, 2);
        p += __shfl_xor_sync(0xffffffffu, p, 1);
        if (lane == 0) {
            float zv = sm.zz[l][grp];
            float sz = zv / (1.f + __expf(-zv));
            sm.yy[l][grp] = (p + uv * Dp) * sz;
        }
    }
    __syncthreads();

    float* y_g = g_y + (size_t)(b * L + l0 + tid) * D + d0;
    float4 v0 = *reinterpret_cast<const float4*>(&sm.yy[tid][0]);
    float4 v1 = *reinterpret_cast<const float4*>(&sm.yy[tid][4]);
    *reinterpret_cast<float4*>(y_g)     = v0;
    *reinterpret_cast<float4*>(y_g + 4) = v1;
}

// ------------------------- launch ------------------------------------------
extern "C" void kernel_launch(void* const* d_in, const int* in_sizes, int n_in,
                              void* d_out, int out_size)
{
    const float* x          = (const float*)d_in[0];
    const float* bp         = (const float*)d_in[1];
    const float* patch_w    = (const float*)d_in[2];
    const float* patch_b    = (const float*)d_in[3];
    const float* in_proj_w  = (const float*)d_in[4];
    const float* conv_w     = (const float*)d_in[5];
    const float* conv_b     = (const float*)d_in[6];
    const float* x_proj_w   = (const float*)d_in[7];
    const float* dt_proj_w  = (const float*)d_in[8];
    const float* dt_proj_b  = (const float*)d_in[9];
    const float* A_log      = (const float*)d_in[10];
    const float* Dskip      = (const float*)d_in[11];
    const float* out_proj_w = (const float*)d_in[12];
    const float* norm_w     = (const float*)d_in[13];
    const float* norm_b     = (const float*)d_in[14];
    const float* fw         = (const float*)d_in[15];
    const float* fb         = (const float*)d_in[16];
    const unsigned char* mask = (const unsigned char*)d_in[17];

    float *tok, *h, *xz, *xc, *dbl, *y;
    cudaGetSymbolAddress((void**)&tok, g_tok);
    cudaGetSymbolAddress((void**)&h,   g_h);
    cudaGetSymbolAddress((void**)&xz,  g_xz);
    cudaGetSymbolAddress((void**)&xc,  g_xc);
    cudaGetSymbolAddress((void**)&dbl, g_dbl);
    cudaGetSymbolAddress((void**)&y,   g_y);

    // patchify: zero tok, split-K=4 accumulate, bias+posembed fused
    zero_k<<<(NTOK * D + 255) / 256, 256>>>(tok, NTOK * D);
    sgemm_patch_k<<<dim3(D / 64, NTOK / 64, 4), 256>>>(x, patch_w, tok);
    posembed_k<<<NTOK, D>>>(bp, mask, patch_b);

    for (int layer = 0; layer < DEPTH; layer++) {
        ln_k<<<NTOK, 128>>>(tok, h, norm_w + layer * D, norm_b + layer * D, dbl, xz);
        sgemm_k<<<dim3((2 * D) / 64, NTOK / 64, 3), 256>>>(h, D,
                in_proj_w + (size_t)layer * D * 2 * D, xz, nullptr, NTOK, 2 * D, D, 0);
        conv_k<<<NTOK, D>>>(conv_w + (size_t)layer * D * 4, conv_b + (size_t)layer * D);
        sgemm_k<<<dim3(1, NTOK / 64, 6), 256>>>(xc, D,
                x_proj_w + (size_t)layer * D * DBL_N, dbl, nullptr, NTOK, DBL_N, D, 0);
        scan_part_k<<<dim3(96, NCH), 128>>>(A_log + (size_t)layer * D * DSTATE,
                                            dt_proj_w + (size_t)layer * DTRANK * D,
                                            dt_proj_b + (size_t)layer * D);
        scan_full_k<<<dim3(96, NCH), 128>>>(A_log + (size_t)layer * D * DSTATE,
                                            Dskip + (size_t)layer * D);
        // out_proj: split-K=3, atomicAdd accumulates residual into tok directly
        sgemm_k<<<dim3(D / 64, NTOK / 64, 3), 256>>>(y, D,
                out_proj_w + (size_t)layer * D * D, tok, nullptr, NTOK, D, D, 3);
    }

    ln_k<<<NTOK, 128>>>(tok, (float*)d_out, fw, fb, nullptr, nullptr);
}

// round 15
// speedup vs baseline: 1.1839x; 1.0117x over previous
#include <cuda_runtime.h>
#include <math.h>
#include <stdint.h>

#define B_SZ 2
#define L 1024
#define D 384
#define PATCH_DIM 4096
#define DEPTH 12
#define DSTATE 16
#define DTRANK 24
#define DBL_N 56
#define NTOK (B_SZ * L)   // 2048
#define NCH 8             // scan chunks
#define CHL (L / NCH)     // 128 steps per chunk
#define SCH 8             // chains per scan block

typedef unsigned long long ull;

// ------------------------- scratch (static device) -------------------------
__device__ float g_tok[NTOK * D];
__device__ float g_h[NTOK * D];
__device__ float g_xz[NTOK * 2 * D];
__device__ float g_xc[NTOK * D];
__device__ float g_dbl[NTOK * DBL_N];
__device__ float g_y[NTOK * D];
__device__ float g_H[96 * NCH * 128];   // inclusive chunk states
__device__ int   g_flag[NCH * 96];      // publish flags (zeroed per layer by ln_k)

// ------------------------- cp.async + f32x2 helpers ------------------------
__device__ __forceinline__ void cp_async16(uint32_t dst, const void* src, bool pred) {
    int sz = pred ? 16 : 0;
    asm volatile("cp.async.ca.shared.global [%0], [%1], 16, %2;\n"
                 :: "r"(dst), "l"(src), "r"(sz));
}
__device__ __forceinline__ void cp_commit() {
    asm volatile("cp.async.commit_group;\n");
}
template <int N>
__device__ __forceinline__ void cp_wait() {
    asm volatile("cp.async.wait_group %0;\n" :: "n"(N));
}
__device__ __forceinline__ ull pack2(float x, float y) {
    ull r; asm("mov.b64 %0, {%1, %2};" : "=l"(r) : "f"(x), "f"(y)); return r;
}
__device__ __forceinline__ void unpack2(ull v, float& x, float& y) {
    asm("mov.b64 {%0, %1}, %2;" : "=f"(x), "=f"(y) : "l"(v));
}
__device__ __forceinline__ void ffma2(ull& d, ull a, ull b) {
    asm("fma.rn.f32x2 %0, %1, %2, %0;" : "+l"(d) : "l"(a), "l"(b));
}

// ------------------------- pipelined SGEMM 64x64 (vector LDS + FFMA2) ------
#define BM 64
#define BN 64
#define BK 16
#define ASTRIDE 20

struct SmemGemm {
    __align__(16) float As[2][BM * ASTRIDE];
    __align__(16) float Bs[2][BK * BN];
};

__device__ __forceinline__ void gemm_inner(const float* __restrict__ As,
                                           const float* __restrict__ Bsr,
                                           int m0, int n0, ull acc2[4][2])
{
    #pragma unroll
    for (int k4 = 0; k4 < BK; k4 += 4) {
        float4 a[4];
        #pragma unroll
        for (int i = 0; i < 4; i++)
            a[i] = *reinterpret_cast<const float4*>(&As[(m0 + i) * ASTRIDE + k4]);
        #pragma unroll
        for (int q = 0; q < 4; q++) {
            float4 bq = *reinterpret_cast<const float4*>(&Bsr[(k4 + q) * BN + n0]);
            ull b01 = pack2(bq.x, bq.y);
            ull b23 = pack2(bq.z, bq.w);
            #pragma unroll
            for (int i = 0; i < 4; i++) {
                const float* af = &a[i].x;
                ull ap = pack2(af[q], af[q]);
                ffma2(acc2[i][0], ap, b01);
                ffma2(acc2[i][1], ap, b23);
            }
        }
    }
}

// epi: 0 none, 1 +bias, 3 C += result.
// gridDim.z>1 -> split-K, partials accumulated via atomicAdd (bias ignored).
__global__ void sgemm_k(const float* __restrict__ A, int lda,
                        const float* __restrict__ Bm,
                        float* __restrict__ C,
                        const float* __restrict__ bias,
                        int M, int N, int K, int epi)
{
    __shared__ SmemGemm sm;
    const int bm = blockIdx.y * BM, bn = blockIdx.x * BN;
    const int tid = threadIdx.x;

    const int ksplit = gridDim.z;
    const int kc = K / ksplit;
    const int kstart = blockIdx.z * kc;
    const int kend = kstart + kc;
    const int niters = (kc + BK - 1) / BK;

    const int am  = tid >> 2;
    const int akq = (tid & 3) << 2;
    const int bkb = tid >> 4;
    const int bn4 = (tid & 15) << 2;
    const bool bn_ok = (bn + bn4) < N;

    const float* Arow = A + (size_t)(bm + am) * lda;

    uint32_t sAs = (uint32_t)__cvta_generic_to_shared(&sm.As[0][0]);
    uint32_t sBs = (uint32_t)__cvta_generic_to_shared(&sm.Bs[0][0]);

    auto load_stage = [&](int it, int buf) {
        int k0 = kstart + it * BK;
        {
            int k = k0 + akq;
            bool p = k < kend;
            const float* src = p ? (Arow + k) : A;
            cp_async16(sAs + (buf * BM * ASTRIDE + am * ASTRIDE + akq) * 4, src, p);
        }
        {
            int k = k0 + bkb;
            bool p = (k < kend) && bn_ok;
            const float* src = p ? (Bm + (size_t)k * N + bn + bn4) : Bm;
            cp_async16(sBs + (buf * BK * BN + bkb * BN + bn4) * 4, src, p);
        }
    };

    const int ty = tid >> 4, tx = tid & 15;
    const int m0 = ty * 4, n0 = tx * 4;

    ull acc2[4][2];
    #pragma unroll
    for (int i = 0; i < 4; i++) { acc2[i][0] = 0ull; acc2[i][1] = 0ull; }

    load_stage(0, 0); cp_commit();
    if (niters > 1) load_stage(1, 1);
    cp_commit();

    for (int it = 0; it < niters; it++) {
        cp_wait<1>();
        __syncthreads();
        const int buf = it & 1;
        gemm_inner(&sm.As[buf][0], &sm.Bs[buf][0], m0, n0, acc2);
        __syncthreads();
        if (it + 2 < niters) load_stage(it + 2, buf);
        cp_commit();
    }

    #pragma unroll
    for (int i = 0; i < 4; i++) {
        int row = bm + m0 + i;
        float v[4];
        unpack2(acc2[i][0], v[0], v[1]);
        unpack2(acc2[i][1], v[2], v[3]);
        #pragma unroll
        for (int j = 0; j < 4; j++) {
            int col = bn + n0 + j;
            if (col < N) {
                size_t off = (size_t)row * N + col;
                float vv = v[j];
                if (ksplit > 1) {
                    atomicAdd(&C[off], vv);
                } else {
                    if (epi == 1) vv += bias[col];
                    if (epi == 3) vv += C[off];
                    C[off] = vv;
                }
            }
        }
    }
}

// ------------------------- patchify GEMM (im2col fused, split-K) -----------
__global__ void sgemm_patch_k(const float* __restrict__ X,
                              const float* __restrict__ Bm,
                              float* __restrict__ C)
{
    __shared__ SmemGemm sm;
    const int bm = blockIdx.y * BM, bn = blockIdx.x * BN;
    const int tid = threadIdx.x;
    const int N = D;

    const int kc = PATCH_DIM / gridDim.z;
    const int kstart = blockIdx.z * kc;
    const int niters = kc / BK;

    const int am  = tid >> 2;
    const int akq = (tid & 3) << 2;
    const int bkb = tid >> 4;
    const int bn4 = (tid & 15) << 2;

    const int m = bm + am;
    const int b = m >> 10, l = m & 1023;
    const int gh = l >> 6, gw = (l >> 3) & 7, gd = l & 7;
    const size_t xbase = ((size_t)(b * 256 + gh * 16) * 256 + gw * 32) * 64 + gd * 8;

    uint32_t sAs = (uint32_t)__cvta_generic_to_shared(&sm.As[0][0]);
    uint32_t sBs = (uint32_t)__cvta_generic_to_shared(&sm.Bs[0][0]);

    auto load_stage = [&](int it, int buf) {
        int k0 = kstart + it * BK;
        {
            int k = k0 + akq;
            int ph = k >> 8, pw = (k >> 3) & 31, pd = k & 7;
            const float* src = X + xbase + (size_t)ph * 16384 + pw * 64 + pd;
            cp_async16(sAs + (buf * BM * ASTRIDE + am * ASTRIDE + akq) * 4, src, true);
        }
        {
            int k = k0 + bkb;
            const float* src = Bm + (size_t)k * N + bn + bn4;
            cp_async16(sBs + (buf * BK * BN + bkb * BN + bn4) * 4, src, true);
        }
    };

    const int ty = tid >> 4, tx = tid & 15;
    const int m0 = ty * 4, n0 = tx * 4;

    ull acc2[4][2];
    #pragma unroll
    for (int i = 0; i < 4; i++) { acc2[i][0] = 0ull; acc2[i][1] = 0ull; }

    load_stage(0, 0); cp_commit();
    load_stage(1, 1); cp_commit();

    for (int it = 0; it < niters; it++) {
        cp_wait<1>();
        __syncthreads();
        const int buf = it & 1;
        gemm_inner(&sm.As[buf][0], &sm.Bs[buf][0], m0, n0, acc2);
        __syncthreads();
        if (it + 2 < niters) load_stage(it + 2, buf);
        cp_commit();
    }

    #pragma unroll
    for (int i = 0; i < 4; i++) {
        int row = bm + m0 + i;
        float v[4];
        unpack2(acc2[i][0], v[0], v[1]);
        unpack2(acc2[i][1], v[2], v[3]);
        #pragma unroll
        for (int j = 0; j < 4; j++)
            atomicAdd(&C[(size_t)row * N + bn + n0 + j], v[j]);
    }
}

// ------------------------- zero buffer --------------------------------------
__global__ void zero_k(float* __restrict__ p, int n) {
    int i = blockIdx.x * blockDim.x + threadIdx.x;
    if (i < n) p[i] = 0.f;
}

// ------------------------- LayerNorm + xz/dbl/flag zeroing -----------------
__global__ void ln_k(const float* __restrict__ in, float* __restrict__ out,
                     const float* __restrict__ w, const float* __restrict__ b,
                     float* __restrict__ zdbl, float* __restrict__ zxz,
                     int* __restrict__ zflag)
{
    int row = blockIdx.x;
    int t = threadIdx.x;   // 128 threads
    if (zdbl != nullptr && t < DBL_N) zdbl[(size_t)row * DBL_N + t] = 0.f;
    if (zxz != nullptr) {
        float* zr = zxz + (size_t)row * (2 * D);
        #pragma unroll
        for (int q = 0; q < 6; q++) zr[t + q * 128] = 0.f;
    }
    if (zflag != nullptr && row < 6) zflag[row * 128 + t] = 0;
    const float* r = in + (size_t)row * D;
    float v0 = r[t], v1 = r[t + 128], v2 = r[t + 256];
    float s = v0 + v1 + v2;
    __shared__ float sh[4], sh2[4];
    #pragma unroll
    for (int o = 16; o; o >>= 1) s += __shfl_xor_sync(~0u, s, o);
    if ((t & 31) == 0) sh[t >> 5] = s;
    __syncthreads();
    float mu = (sh[0] + sh[1] + sh[2] + sh[3]) * (1.f / 384.f);
    float d0 = v0 - mu, d1 = v1 - mu, d2 = v2 - mu;
    float q = d0 * d0 + d1 * d1 + d2 * d2;
    #pragma unroll
    for (int o = 16; o; o >>= 1) q += __shfl_xor_sync(~0u, q, o);
    if ((t & 31) == 0) sh2[t >> 5] = q;
    __syncthreads();
    float var = (sh2[0] + sh2[1] + sh2[2] + sh2[3]) * (1.f / 384.f);
    float rs = rsqrtf(var + 1e-5f);
    float* o = out + (size_t)row * D;
    o[t]       = d0 * rs * w[t]       + b[t];
    o[t + 128] = d1 * rs * w[t + 128] + b[t + 128];
    o[t + 256] = d2 * rs * w[t + 256] + b[t + 256];
}

// ------------------------- positional embedding + patch bias ---------------
__global__ void posembed_k(const float* __restrict__ bp,
                           const unsigned char* __restrict__ mask,
                           const float* __restrict__ patch_b)
{
    int row = blockIdx.x;           // NTOK
    int d = threadIdx.x;            // 384
    int b = row >> 10, l = row & 1023;
    int gh = l >> 6, gw = (l >> 3) & 7, gd = l & 7;
    float vr = bp[b * 4 + 2];
    bool m = mask[b] != 0;
    int j = d / 128, r = d - j * 128, f = r & 63;
    float c;
    if (j == 0)      c = (float)gh * (1.f / 15.f);
    else if (j == 1) c = ((float)gw - 4.f) * 0.25f;
    else {
        float v = m ? ((float)gd - 4.f) * vr : (float)gd * vr;
        float den = m ? 4.f * vr : 7.f * vr;
        c = v / den;
    }
    float omega = powf(10000.f, -(float)f * (1.f / 64.f));
    float ph = c * omega;
    float pe = (r < 64) ? sinf(ph) : cosf(ph);
    g_tok[(size_t)row * D + d] += pe + patch_b[d];
}

// ------------------------- causal depthwise conv + silu --------------------
__global__ void conv_k(const float* __restrict__ cw, const float* __restrict__ cb)
{
    int row = blockIdx.x;           // NTOK
    int d = threadIdx.x;            // 384
    int l = row & 1023, b = row >> 10;
    float acc = cb[d];
    #pragma unroll
    for (int j = 0; j < 4; j++) {
        int ll = l - 3 + j;
        if (ll >= 0)
            acc = fmaf(g_xz[(size_t)((b << 10) + ll) * (2 * D) + d], cw[d * 4 + j], acc);
    }
    g_xc[(size_t)row * D + d] = acc / (1.f + __expf(-acc));
}

// ------------------------- single-pass chunked scan ------------------------
// Grid (96, NCH), 128 thr. One kernel: stage -> inline dt_proj -> local scan
// (P,W) -> chained cross-block prefix publish (spin on predecessor chunk's
// flag; forward progress: predecessor has lower linear block id) -> replay.
// zz/yy alias the dead dtr region (saves smem; keeps 6 blocks/SM -> all 768
// blocks co-resident in one wave).
struct ScanTile {
    __align__(16) float dtr[CHL][DTRANK];  // 12 KB; reused as zz|yy after dt
    __align__(16) float xc[CHL][SCH];      //  4 KB
    __align__(16) float bc[CHL][32];       // 16 KB  B[16] | C[16]
    __align__(16) float dt[CHL][SCH];      //  4 KB
    __align__(16) float dtw[DTRANK][SCH];  // 768 B
    float dtb[SCH];
};

__global__ void scan_k(const float* __restrict__ A_log,
                       const float* __restrict__ dtw,
                       const float* __restrict__ dtb,
                       const float* __restrict__ Dsk)
{
    __shared__ ScanTile sm;
    const int tid = threadIdx.x;
    const int grp = tid >> 4, lane = tid & 15;
    const int c = blockIdx.y;
    const int blk = blockIdx.x;             // 0..95
    const int b = blk / 48;
    const int d0 = (blk % 48) * SCH;
    const int d = d0 + grp;
    const int l0 = c * CHL;

    const float* dbl_b = g_dbl + (size_t)b * L * DBL_N;
    const float* xc_g  = g_xc + (size_t)b * L * D;

    uint32_t s_dtr = (uint32_t)__cvta_generic_to_shared(&sm.dtr[0][0]);
    uint32_t s_xc  = (uint32_t)__cvta_generic_to_shared(&sm.xc[0][0]);
    uint32_t s_bc  = (uint32_t)__cvta_generic_to_shared(&sm.bc[0][0]);
    uint32_t s_dtw = (uint32_t)__cvta_generic_to_shared(&sm.dtw[0][0]);

    // stage dtr (dbl[:, :24]), xc, bc, dtw, dtb
    #pragma unroll
    for (int q = 0; q < 6; q++) {
        int qq = tid + q * 128;
        int row = qq / 6, part = (qq % 6) << 2;
        cp_async16(s_dtr + (row * DTRANK + part) * 4,
                   dbl_b + (size_t)(l0 + row) * DBL_N + part, true);
    }
    #pragma unroll
    for (int q = 0; q < 2; q++) {
        int qq = tid + q * 128;
        int row = qq >> 1, part = (qq & 1) << 2;
        cp_async16(s_xc + (row * SCH + part) * 4,
                   xc_g + (size_t)(l0 + row) * D + d0 + part, true);
    }
    #pragma unroll
    for (int q = 0; q < 8; q++) {
        int qq = tid + q * 128;
        int row = qq >> 3, part = (qq & 7) << 2;
        cp_async16(s_bc + (row * 32 + part) * 4,
                   dbl_b + (size_t)(l0 + row) * DBL_N + DTRANK + part, true);
    }
    if (tid < 48) {
        int r = tid >> 1, part = (tid & 1) << 2;
        cp_async16(s_dtw + (r * SCH + part) * 4,
                   dtw + (size_t)r * D + d0 + part, true);
    }
    if (tid < SCH) sm.dtb[tid] = __ldg(&dtb[d0 + tid]);
    cp_commit();

    const float Aa = -__expf(A_log[d * DSTATE + lane]);
    const float Dp = __ldg(&Dsk[d]);

    cp_wait<0>();
    __syncthreads();

    // inline dt_proj: thread = row tid
    {
        float acc[SCH];
        #pragma unroll
        for (int j = 0; j < SCH; j++) acc[j] = sm.dtb[j];
        #pragma unroll
        for (int r = 0; r < DTRANK; r += 4) {
            float4 v = *reinterpret_cast<const float4*>(&sm.dtr[tid][r]);
            const float* vf = &v.x;
            #pragma unroll
            for (int cc = 0; cc < 4; cc++)
                #pragma unroll
                for (int j = 0; j < SCH; j++)
                    acc[j] = fmaf(vf[cc], sm.dtw[r + cc][j], acc[j]);
        }
        #pragma unroll
        for (int j = 0; j < SCH; j++)
            sm.dt[tid][j] = (acc[j] > 20.f) ? acc[j] : log1pf(__expf(acc[j]));
    }
    __syncthreads();   // dtr reads complete -> region reusable

    // stage zz into the dead dtr region (overlaps local scan + chain)
    float* zzp = &sm.dtr[0][0];                 // [CHL][SCH]
    float* yyp = zzp + CHL * SCH;               // [CHL][SCH]
    {
        uint32_t s_zz = (uint32_t)__cvta_generic_to_shared(zzp);
        const float* z_g = g_xz + (size_t)b * L * (2 * D) + D;
        #pragma unroll
        for (int q = 0; q < 2; q++) {
            int qq = tid + q * 128;
            int row = qq >> 1, part = (qq & 1) << 2;
            cp_async16(s_zz + (row * SCH + part) * 4,
                       z_g + (size_t)(l0 + row) * (2 * D) + d0 + part, true);
        }
        cp_commit();
    }

    // local scan with h0 = 0 -> (P, W) per (chain grp, state lane)
    float h = 0.f, P = 1.f;
    #pragma unroll 8
    for (int l = 0; l < CHL; l++) {
        float dtv = sm.dt[l][grp];
        float uv  = sm.xc[l][grp];
        float Bv  = sm.bc[l][lane];
        float dA  = __expf(dtv * Aa);
        h = fmaf(h, dA, dtv * uv * Bv);
        P *= dA;
    }

    // chained prefix: wait predecessor chunk, fold, publish inclusive state
    float hprev = 0.f;
    if (c > 0) {
        if (tid == 0) {
            volatile int* f = &g_flag[(c - 1) * 96 + blk];
            while (*f == 0) { }
        }
        __syncthreads();
        volatile float* hp = &g_H[((size_t)blk * NCH + (c - 1)) * 128 + tid];
        hprev = *hp;
    }
    float Hc = fmaf(hprev, P, hprev == 0.f && c == 0 ? h * 0.f + h - h + h : h); // placeholder avoided below
    Hc = fmaf(hprev, P, h);   // h currently holds W (local end state)
    g_H[((size_t)blk * NCH + c) * 128 + tid] = Hc;
    __threadfence();
    __syncthreads();
    if (tid == 0) atomicExch(&g_flag[c * 96 + blk], 1);

    // replay with true h0 = hprev
    cp_wait<0>();
    __syncthreads();
    h = hprev;
    #pragma unroll 8
    for (int l = 0; l < CHL; l++) {
        float dtv = sm.dt[l][grp];
        float uv  = sm.xc[l][grp];
        float Bv  = sm.bc[l][lane];
        float Cv  = sm.bc[l][lane + 16];
        float dA  = __expf(dtv * Aa);
        h = fmaf(h, dA, dtv * uv * Bv);
        float p = h * Cv;
        p += __shfl_xor_sync(0xffffffffu, p, 8);
        p += __shfl_xor_sync(0xffffffffu, p, 4);
        p += __shfl_xor_sync(0xffffffffu, p, 2);
        p += __shfl_xor_sync(0xffffffffu, p, 1);
        if (lane == 0) {
            float zv = zzp[l * SCH + grp];
            float sz = zv / (1.f + __expf(-zv));
            yyp[l * SCH + grp] = (p + uv * Dp) * sz;
        }
    }
    __syncthreads();

    float* y_g = g_y + (size_t)(b * L + l0 + tid) * D + d0;
    float4 v0 = *reinterpret_cast<const float4*>(&yyp[tid * SCH]);
    float4 v1 = *reinterpret_cast<const float4*>(&yyp[tid * SCH + 4]);
    *reinterpret_cast<float4*>(y_g)     = v0;
    *reinterpret_cast<float4*>(y_g + 4) = v1;
}

// ------------------------- launch ------------------------------------------
extern "C" void kernel_launch(void* const* d_in, const int* in_sizes, int n_in,
                              void* d_out, int out_size)
{
    const float* x          = (const float*)d_in[0];
    const float* bp         = (const float*)d_in[1];
    const float* patch_w    = (const float*)d_in[2];
    const float* patch_b    = (const float*)d_in[3];
    const float* in_proj_w  = (const float*)d_in[4];
    const float* conv_w     = (const float*)d_in[5];
    const float* conv_b     = (const float*)d_in[6];
    const float* x_proj_w   = (const float*)d_in[7];
    const float* dt_proj_w  = (const float*)d_in[8];
    const float* dt_proj_b  = (const float*)d_in[9];
    const float* A_log      = (const float*)d_in[10];
    const float* Dskip      = (const float*)d_in[11];
    const float* out_proj_w = (const float*)d_in[12];
    const float* norm_w     = (const float*)d_in[13];
    const float* norm_b     = (const float*)d_in[14];
    const float* fw         = (const float*)d_in[15];
    const float* fb         = (const float*)d_in[16];
    const unsigned char* mask = (const unsigned char*)d_in[17];

    float *tok, *h, *xz, *xc, *dbl, *y;
    int* flg;
    cudaGetSymbolAddress((void**)&tok, g_tok);
    cudaGetSymbolAddress((void**)&h,   g_h);
    cudaGetSymbolAddress((void**)&xz,  g_xz);
    cudaGetSymbolAddress((void**)&xc,  g_xc);
    cudaGetSymbolAddress((void**)&dbl, g_dbl);
    cudaGetSymbolAddress((void**)&y,   g_y);
    cudaGetSymbolAddress((void**)&flg, g_flag);

    // patchify: zero tok, split-K=4 accumulate, bias+posembed fused
    zero_k<<<(NTOK * D + 255) / 256, 256>>>(tok, NTOK * D);
    sgemm_patch_k<<<dim3(D / 64, NTOK / 64, 4), 256>>>(x, patch_w, tok);
    posembed_k<<<NTOK, D>>>(bp, mask, patch_b);

    for (int layer = 0; layer < DEPTH; layer++) {
        ln_k<<<NTOK, 128>>>(tok, h, norm_w + layer * D, norm_b + layer * D,
                            dbl, xz, flg);
        sgemm_k<<<dim3((2 * D) / 64, NTOK / 64, 3), 256>>>(h, D,
                in_proj_w + (size_t)layer * D * 2 * D, xz, nullptr, NTOK, 2 * D, D, 0);
        conv_k<<<NTOK, D>>>(conv_w + (size_t)layer * D * 4, conv_b + (size_t)layer * D);
        sgemm_k<<<dim3(1, NTOK / 64, 6), 256>>>(xc, D,
                x_proj_w + (size_t)layer * D * DBL_N, dbl, nullptr, NTOK, DBL_N, D, 0);
        scan_k<<<dim3(96, NCH), 128>>>(A_log + (size_t)layer * D * DSTATE,
                                       dt_proj_w + (size_t)layer * DTRANK * D,
                                       dt_proj_b + (size_t)layer * D,
                                       Dskip + (size_t)layer * D);
        sgemm_k<<<dim3(D / 64, NTOK / 64, 3), 256>>>(y, D,
                out_proj_w + (size_t)layer * D * D, tok, nullptr, NTOK, D, D, 3);
    }

    ln_k<<<NTOK, 128>>>(tok, (float*)d_out, fw, fb, nullptr, nullptr, nullptr);
}